// round 17
// baseline (speedup 1.0000x reference)
#include <cuda_runtime.h>
#include <cuda_fp16.h>
#include <cstdint>
#include <math.h>

#define BATCH 4
#define SEQ   2048
#define DMODEL 1024

// smem: BK=128 int8 -> 128B rows; planes A0|A1|B0|B1 16KB each; 3 stages
#define PLANE_BYTES  16384
#define STAGE_BYTES  (4 * PLANE_BYTES)      // 64KB
#define NSTAGE       3
#define SMEM_TOTAL   (NSTAGE * STAGE_BYTES) // 192KB
#define NTHREADS     512

// ======================= scratch ============================================
__device__ __align__(16) char g_E0[BATCH * SEQ * DMODEL];
__device__ __align__(16) char g_E1[BATCH * SEQ * DMODEL];
__device__ __align__(16) char g_W0[3 * DMODEL * DMODEL];
__device__ __align__(16) char g_W1[3 * DMODEL * DMODEL];
__device__ __align__(16) char g_Q0[BATCH * SEQ * DMODEL];
__device__ __align__(16) char g_Q1[BATCH * SEQ * DMODEL];
__device__ __align__(16) char g_K0[BATCH * SEQ * DMODEL];
__device__ __align__(16) char g_K1[BATCH * SEQ * DMODEL];
__device__ __align__(16) char g_Vt0[BATCH * DMODEL * SEQ];   // [b][d][s]
__device__ __align__(16) char g_Vt1[BATCH * DMODEL * SEQ];
__device__ __align__(16) char g_P0[BATCH * SEQ * SEQ];
__device__ __align__(16) char g_P1[BATCH * SEQ * SEQ];
__device__ __align__(16) __half g_Qh[BATCH * SEQ * DMODEL];  // fp16 staging
__device__ __align__(16) __half g_Kh[BATCH * SEQ * DMODEL];
__device__ __align__(16) __half g_Vth[BATCH * DMODEL * SEQ];
__device__ float g_sE[BATCH * SEQ];
__device__ float g_sW[3 * DMODEL];
__device__ float g_sQ[BATCH * SEQ];
__device__ float g_sK[BATCH * SEQ];
__device__ float g_sVt[BATCH * DMODEL];
__device__ float g_sP[BATCH * SEQ];
__device__ float g_mags[BATCH * SEQ];
__device__ float g_thresh;

__device__ __forceinline__ uint32_t smem_u32(const void* p) {
    uint32_t a;
    asm("{ .reg .u64 t; cvta.to.shared.u64 t, %1; cvt.u32.u64 %0, t; }" : "=r"(a) : "l"(p));
    return a;
}
__device__ __forceinline__ void cp16(uint32_t dst, const void* src) {
    asm volatile("cp.async.cg.shared.global [%0], [%1], 16;" :: "r"(dst), "l"(src));
}
#define CP_COMMIT() asm volatile("cp.async.commit_group;" ::: "memory")
#define CP_WAIT1()  asm volatile("cp.async.wait_group 1;" ::: "memory")
#define CP_WAIT0()  asm volatile("cp.async.wait_group 0;" ::: "memory")

__device__ __forceinline__ void ldm4(uint32_t f[4], uint32_t addr) {
    asm volatile("ldmatrix.sync.aligned.m8n8.x4.shared.b16 {%0,%1,%2,%3}, [%4];"
        : "=r"(f[0]), "=r"(f[1]), "=r"(f[2]), "=r"(f[3]) : "r"(addr));
}
__device__ __forceinline__ void imma(int c[4], const uint32_t a[4],
                                     uint32_t b0, uint32_t b1) {
    asm volatile(
        "mma.sync.aligned.m16n8k32.row.col.s32.s8.s8.s32 "
        "{%0,%1,%2,%3}, {%4,%5,%6,%7}, {%8,%9}, {%0,%1,%2,%3};"
        : "+r"(c[0]), "+r"(c[1]), "+r"(c[2]), "+r"(c[3])
        : "r"(a[0]), "r"(a[1]), "r"(a[2]), "r"(a[3]), "r"(b0), "r"(b1));
}

__device__ __forceinline__ void quant2(float x, float inv, char& q0, char& q1) {
    float t = x * inv;
    int a = __float2int_rn(t);
    int b = __float2int_rn((t - (float)a) * 128.0f);
    q0 = (char)a;
    q1 = (char)b;
}

// ======================= quantize rows (fp32 src, + optional L2 norm) =======
__device__ __forceinline__ void quant_body_f32(
    const float* __restrict__ src, char* __restrict__ L0, char* __restrict__ L1,
    float* __restrict__ scl, int C, float* __restrict__ mags_out, int row)
{
    int tid = threadIdx.x;
    const float4* p = (const float4*)(src + (size_t)row * C);
    int n4 = C >> 2;
    float mx = 0.0f, sq = 0.0f;
    for (int i = tid; i < n4; i += 256) {
        float4 v = p[i];
        mx = fmaxf(mx, fmaxf(fmaxf(fabsf(v.x), fabsf(v.y)),
                             fmaxf(fabsf(v.z), fabsf(v.w))));
        if (mags_out) sq += v.x * v.x + v.y * v.y + v.z * v.z + v.w * v.w;
    }
    __shared__ float sm[256];
    __shared__ float ss[256];
    sm[tid] = mx;
    ss[tid] = sq;
    __syncthreads();
    for (int off = 128; off > 0; off >>= 1) {
        if (tid < off) {
            sm[tid] = fmaxf(sm[tid], sm[tid + off]);
            ss[tid] += ss[tid + off];
        }
        __syncthreads();
    }
    float s = sm[0] * (1.0f / 127.0f);
    float inv = (s > 0.0f) ? 1.0f / s : 0.0f;
    if (tid == 0) {
        scl[row] = (s > 0.0f) ? s : 1.0f;
        if (mags_out) mags_out[row] = sqrtf(ss[0]);
    }
    char* l0 = L0 + (size_t)row * C;
    char* l1 = L1 + (size_t)row * C;
    for (int i = tid; i < n4; i += 256) {
        float4 v = p[i];
        char a0, a1, b0, b1, c0, c1, d0, d1;
        quant2(v.x, inv, a0, a1); quant2(v.y, inv, b0, b1);
        quant2(v.z, inv, c0, c1); quant2(v.w, inv, d0, d1);
        ((char4*)l0)[i] = make_char4(a0, b0, c0, d0);
        ((char4*)l1)[i] = make_char4(a1, b1, c1, d1);
    }
}

__global__ void quant_E(const float* __restrict__ E) {
    quant_body_f32(E, g_E0, g_E1, g_sE, DMODEL, g_mags, blockIdx.x);
}

__global__ void quant_W(const float* __restrict__ Wq, const float* __restrict__ Wk,
                        const float* __restrict__ Wv) {
    int y = blockIdx.y;
    const float* src = (y == 0) ? Wq : (y == 1) ? Wk : Wv;
    quant_body_f32(src, g_W0 + (size_t)y * DMODEL * DMODEL,
                   g_W1 + (size_t)y * DMODEL * DMODEL,
                   g_sW + y * DMODEL, DMODEL, nullptr, blockIdx.x);
}

// ======================= quantize rows (fp16 src) ===========================
__device__ __forceinline__ void quant_body_f16(
    const __half* __restrict__ src, char* __restrict__ L0, char* __restrict__ L1,
    float* __restrict__ scl, int C, int row)
{
    int tid = threadIdx.x;
    const __half2* p = (const __half2*)(src + (size_t)row * C);
    int n2 = C >> 1;
    float mx = 0.0f;
    for (int i = tid; i < n2; i += 256) {
        float2 f = __half22float2(p[i]);
        mx = fmaxf(mx, fmaxf(fabsf(f.x), fabsf(f.y)));
    }
    __shared__ float sm[256];
    sm[tid] = mx;
    __syncthreads();
    for (int off = 128; off > 0; off >>= 1) {
        if (tid < off) sm[tid] = fmaxf(sm[tid], sm[tid + off]);
        __syncthreads();
    }
    float s = sm[0] * (1.0f / 127.0f);
    float inv = (s > 0.0f) ? 1.0f / s : 0.0f;
    if (tid == 0) scl[row] = (s > 0.0f) ? s : 1.0f;
    char* l0 = L0 + (size_t)row * C;
    char* l1 = L1 + (size_t)row * C;
    int n4 = C >> 2;
    for (int i = tid; i < n4; i += 256) {
        float2 fa = __half22float2(p[i * 2]);
        float2 fb = __half22float2(p[i * 2 + 1]);
        char a0, a1, b0, b1, c0, c1, d0, d1;
        quant2(fa.x, inv, a0, a1); quant2(fa.y, inv, b0, b1);
        quant2(fb.x, inv, c0, c1); quant2(fb.y, inv, d0, d1);
        ((char4*)l0)[i] = make_char4(a0, b0, c0, d0);
        ((char4*)l1)[i] = make_char4(a1, b1, c1, d1);
    }
}

__global__ void quant_QK() {
    if (blockIdx.y == 0)
        quant_body_f16(g_Qh, g_Q0, g_Q1, g_sQ, DMODEL, blockIdx.x);
    else
        quant_body_f16(g_Kh, g_K0, g_K1, g_sK, DMODEL, blockIdx.x);
}
__global__ void quant_Vt() {
    quant_body_f16(g_Vth, g_Vt0, g_Vt1, g_sVt, SEQ, blockIdx.x);
}

__global__ void thresh_kernel() {
    int tid = threadIdx.x;
    __shared__ double sd[256];
    double total = 0.0;
    for (int b = 0; b < BATCH; b++) {
        double local = 0.0;
        for (int i = tid; i < SEQ; i += 256) local += (double)g_mags[b * SEQ + i];
        sd[tid] = local;
        __syncthreads();
        for (int off = 128; off > 0; off >>= 1) {
            if (tid < off) sd[tid] += sd[tid + off];
            __syncthreads();
        }
        if (tid == 0) total += sd[0] * sd[0];
        __syncthreads();
    }
    if (tid == 0) g_thresh = (float)(total / ((double)BATCH * SEQ * SEQ));
}

// ======================= softmax (+ inline P quantization) ==================
__global__ void softmax_kernel(float* __restrict__ w) {
    size_t row = blockIdx.x;
    float4* p = (float4*)(w + row * SEQ);
    int tid = threadIdx.x;
    float4 v0 = p[tid];
    float4 v1 = p[tid + 256];
    float m = fmaxf(fmaxf(fmaxf(v0.x, v0.y), fmaxf(v0.z, v0.w)),
                    fmaxf(fmaxf(v1.x, v1.y), fmaxf(v1.z, v1.w)));
    __shared__ float sm[256];
    sm[tid] = m;
    __syncthreads();
    for (int off = 128; off > 0; off >>= 1) {
        if (tid < off) sm[tid] = fmaxf(sm[tid], sm[tid + off]);
        __syncthreads();
    }
    m = sm[0];
    __syncthreads();
    v0.x = expf(v0.x - m); v0.y = expf(v0.y - m);
    v0.z = expf(v0.z - m); v0.w = expf(v0.w - m);
    v1.x = expf(v1.x - m); v1.y = expf(v1.y - m);
    v1.z = expf(v1.z - m); v1.w = expf(v1.w - m);
    float s = v0.x + v0.y + v0.z + v0.w + v1.x + v1.y + v1.z + v1.w;
    sm[tid] = s;
    __syncthreads();
    for (int off = 128; off > 0; off >>= 1) {
        if (tid < off) sm[tid] += sm[tid + off];
        __syncthreads();
    }
    float inv = 1.0f / sm[0];
    if (tid == 0) g_sP[row] = inv * (1.0f / 127.0f);

    char q0[8], q1[8];
    quant2(v0.x * 127.0f, 1.0f, q0[0], q1[0]);
    quant2(v0.y * 127.0f, 1.0f, q0[1], q1[1]);
    quant2(v0.z * 127.0f, 1.0f, q0[2], q1[2]);
    quant2(v0.w * 127.0f, 1.0f, q0[3], q1[3]);
    quant2(v1.x * 127.0f, 1.0f, q0[4], q1[4]);
    quant2(v1.y * 127.0f, 1.0f, q0[5], q1[5]);
    quant2(v1.z * 127.0f, 1.0f, q0[6], q1[6]);
    quant2(v1.w * 127.0f, 1.0f, q0[7], q1[7]);
    ((char4*)(g_P0 + row * SEQ))[tid] = make_char4(q0[0], q0[1], q0[2], q0[3]);
    ((char4*)(g_P1 + row * SEQ))[tid] = make_char4(q1[0], q1[1], q1[2], q1[3]);
    ((char4*)(g_P0 + row * SEQ))[tid + 256] = make_char4(q0[4], q0[5], q0[6], q0[7]);
    ((char4*)(g_P1 + row * SEQ))[tid + 256] = make_char4(q1[4], q1[5], q1[6], q1[7]);

    v0.x *= inv; v0.y *= inv; v0.z *= inv; v0.w *= inv;
    v1.x *= inv; v1.y *= inv; v1.z *= inv; v1.w *= inv;
    p[tid] = v0;
    p[tid + 256] = v1;
}

// ======================= pipelined IMMA GEMM core ===========================
// C[128x128]/CTA, 16 warps (4x4) each 32x32, BK=128 int8, 3-stage ring.
__device__ __forceinline__ void load_stage(
    uint32_t sb, int slot, int row, int qs,
    const char* __restrict__ A0, const char* __restrict__ A1,
    const char* __restrict__ B0, const char* __restrict__ B1,
    int lda, int ldb, int m0, int n0, int k0)
{
    uint32_t drow = sb + (uint32_t)slot * STAGE_BYTES + (uint32_t)row * 128;
    const char* a0 = A0 + (size_t)(m0 + row) * lda + k0;
    const char* a1 = A1 + (size_t)(m0 + row) * lda + k0;
    const char* b0 = B0 + (size_t)(n0 + row) * ldb + k0;
    const char* b1 = B1 + (size_t)(n0 + row) * ldb + k0;
    #pragma unroll
    for (int i = 0; i < 2; i++) {
        int seg = qs * 2 + i;
        uint32_t sw = (uint32_t)((seg ^ (row & 7)) * 16);
        cp16(drow + sw,                   a0 + seg * 16);
        cp16(drow + sw + PLANE_BYTES,     a1 + seg * 16);
        cp16(drow + sw + 2 * PLANE_BYTES, b0 + seg * 16);
        cp16(drow + sw + 3 * PLANE_BYTES, b1 + seg * 16);
    }
}

__device__ __forceinline__ void gemm_run(
    const char* __restrict__ A0, const char* __restrict__ A1,
    const char* __restrict__ B0, const char* __restrict__ B1,
    int lda, int ldb, int K, int m0, int n0,
    int acc0[2][4][4], int accX[2][4][4])
{
    extern __shared__ __align__(16) char smem[];
    uint32_t sb = smem_u32(smem);
    int tid = threadIdx.x, lane = tid & 31, warp = tid >> 5;
    int wm = (warp >> 2) * 32, wn = (warp & 3) * 32;
    int row = tid >> 2, qs = tid & 3;
    int g = lane >> 3, r = lane & 7;
    int rb = (g & 1) * 8 + r, hsel = g >> 1;

    int NC = K >> 7;   // BK=128 int8
    #pragma unroll
    for (int s = 0; s < NSTAGE - 1; s++) {
        load_stage(sb, s, row, qs, A0, A1, B0, B1, lda, ldb, m0, n0, s * 128);
        CP_COMMIT();
    }

    uint32_t arow = (uint32_t)((wm + rb) * 128);
    uint32_t brow = (uint32_t)((wn + rb) * 128);

    for (int c = 0; c < NC; c++) {
        if (c == NC - 1) CP_WAIT0(); else CP_WAIT1();
        __syncthreads();
        if (c + 2 < NC) {
            load_stage(sb, (c + 2) % NSTAGE, row, qs, A0, A1, B0, B1,
                       lda, ldb, m0, n0, (c + 2) * 128);
            CP_COMMIT();
        }
        uint32_t st = sb + (uint32_t)(c % NSTAGE) * STAGE_BYTES;
        #pragma unroll
        for (int kb = 0; kb < 4; kb++) {
            uint32_t segoff = (uint32_t)((((kb * 2) | hsel) ^ r) * 16);
            uint32_t a0f[2][4], a1f[2][4], b0f[2][4], b1f[2][4];
            #pragma unroll
            for (int mi = 0; mi < 2; mi++) {
                uint32_t ad = st + arow + (uint32_t)(mi * 16 * 128) + segoff;
                ldm4(a0f[mi], ad);
                ldm4(a1f[mi], ad + PLANE_BYTES);
            }
            #pragma unroll
            for (int nb = 0; nb < 2; nb++) {
                uint32_t bd = st + 2 * PLANE_BYTES + brow + (uint32_t)(nb * 16 * 128) + segoff;
                ldm4(b0f[nb], bd);
                ldm4(b1f[nb], bd + PLANE_BYTES);
            }
            #pragma unroll
            for (int mi = 0; mi < 2; mi++)
                #pragma unroll
                for (int nb = 0; nb < 2; nb++)
                    #pragma unroll
                    for (int s = 0; s < 2; s++) {
                        int ni = nb * 2 + s;
                        imma(acc0[mi][ni], a0f[mi], b0f[nb][s], b0f[nb][s + 2]);
                        imma(accX[mi][ni], a0f[mi], b1f[nb][s], b1f[nb][s + 2]);
                        imma(accX[mi][ni], a1f[mi], b0f[nb][s], b0f[nb][s + 2]);
                    }
        }
    }
}

#define COMBINE(mi, ni, j) ((float)acc0[mi][ni][j] + (float)accX[mi][ni][j] * 0.0078125f)

// ======================= GEMM kernels =======================================
__global__ void __launch_bounds__(NTHREADS, 1) qkv_tc(int z_base) {
    int z = z_base + blockIdx.z;
    const char* Bw0 = g_W0 + (size_t)z * DMODEL * DMODEL;
    const char* Bw1 = g_W1 + (size_t)z * DMODEL * DMODEL;
    int m0 = blockIdx.y * 128, n0 = blockIdx.x * 128;
    int acc0[2][4][4] = {}, accX[2][4][4] = {};
    gemm_run(g_E0, g_E1, Bw0, Bw1, DMODEL, DMODEL, DMODEL, m0, n0, acc0, accX);

    int lane = threadIdx.x & 31, warp = threadIdx.x >> 5;
    int wm = (warp >> 2) * 32, wn = (warp & 3) * 32;
    #pragma unroll
    for (int mi = 0; mi < 2; mi++)
        #pragma unroll
        for (int h = 0; h < 2; h++) {
            int rg = m0 + wm + mi * 16 + h * 8 + (lane >> 2);
            float sa = g_sE[rg];
            #pragma unroll
            for (int ni = 0; ni < 4; ni++) {
                int col = n0 + wn + ni * 8 + (lane & 3) * 2;
                float sb0 = g_sW[z * DMODEL + col];
                float sb1 = g_sW[z * DMODEL + col + 1];
                float x0 = sa * sb0 * COMBINE(mi, ni, h * 2);
                float x1 = sa * sb1 * COMBINE(mi, ni, h * 2 + 1);
                if (z == 2) {
                    int b = rg >> 11, s = rg & (SEQ - 1);
                    __half* vb = g_Vth + (size_t)b * DMODEL * SEQ;
                    vb[(size_t)col * SEQ + s] = __float2half_rn(x0);
                    vb[(size_t)(col + 1) * SEQ + s] = __float2half_rn(x1);
                } else {
                    __half* C = (z == 0) ? g_Qh : g_Kh;
                    __half2 h2 = __floats2half2_rn(x0, x1);
                    *(__half2*)&C[(size_t)rg * DMODEL + col] = h2;
                }
            }
        }
}

__global__ void __launch_bounds__(NTHREADS, 1) scores_tc(
    const float* __restrict__ intent_bias, const int* __restrict__ mask,
    float* __restrict__ wts)
{
    int b = blockIdx.z;
    size_t off = (size_t)b * SEQ * DMODEL;
    int m0 = blockIdx.y * 128, n0 = blockIdx.x * 128;
    int acc0[2][4][4] = {}, accX[2][4][4] = {};
    gemm_run(g_Q0 + off, g_Q1 + off, g_K0 + off, g_K1 + off,
             DMODEL, DMODEL, DMODEL, m0, n0, acc0, accX);

    int lane = threadIdx.x & 31, warp = threadIdx.x >> 5;
    int wm = (warp >> 2) * 32, wn = (warp & 3) * 32;
    float th = g_thresh;
    float bias = intent_bias[0];
    #pragma unroll
    for (int mi = 0; mi < 2; mi++)
        #pragma unroll
        for (int h = 0; h < 2; h++) {
            int q = m0 + wm + mi * 16 + h * 8 + (lane >> 2);
            float mq = g_mags[b * SEQ + q];
            float sa = g_sQ[b * SEQ + q] * 0.03125f;
            size_t rb2 = ((size_t)b * SEQ + q) * SEQ;
            #pragma unroll
            for (int ni = 0; ni < 4; ni++) {
                int col = n0 + wn + ni * 8 + (lane & 3) * 2;
                float x0 = sa * g_sK[b * SEQ + col] * COMBINE(mi, ni, h * 2);
                float x1 = sa * g_sK[b * SEQ + col + 1] * COMBINE(mi, ni, h * 2 + 1);
                float mk0 = g_mags[b * SEQ + col];
                float mk1 = g_mags[b * SEQ + col + 1];
                if (mq * mk0 > th) x0 += bias;
                if (mq * mk1 > th) x1 += bias;
                int2 mv = *(const int2*)&mask[rb2 + col];
                if (mv.x == 0) x0 = -1e9f;
                if (mv.y == 0) x1 = -1e9f;
                *(float2*)&wts[rb2 + col] = make_float2(x0, x1);
            }
        }
}

__global__ void __launch_bounds__(NTHREADS, 1) av_tc(float* __restrict__ att) {
    int b = blockIdx.z;
    size_t po = (size_t)b * SEQ * SEQ;
    size_t vo = (size_t)b * DMODEL * SEQ;
    int m0 = blockIdx.y * 128, n0 = blockIdx.x * 128;
    int acc0[2][4][4] = {}, accX[2][4][4] = {};
    gemm_run(g_P0 + po, g_P1 + po, g_Vt0 + vo, g_Vt1 + vo,
             SEQ, SEQ, SEQ, m0, n0, acc0, accX);

    int lane = threadIdx.x & 31, warp = threadIdx.x >> 5;
    int wm = (warp >> 2) * 32, wn = (warp & 3) * 32;
    #pragma unroll
    for (int mi = 0; mi < 2; mi++)
        #pragma unroll
        for (int h = 0; h < 2; h++) {
            int s = m0 + wm + mi * 16 + h * 8 + (lane >> 2);
            float sa = g_sP[b * SEQ + s];
            #pragma unroll
            for (int ni = 0; ni < 4; ni++) {
                int col = n0 + wn + ni * 8 + (lane & 3) * 2;
                float x0 = sa * g_sVt[b * DMODEL + col] * COMBINE(mi, ni, h * 2);
                float x1 = sa * g_sVt[b * DMODEL + col + 1] * COMBINE(mi, ni, h * 2 + 1);
                *(float2*)&att[((size_t)b * SEQ + s) * DMODEL + col] =
                    make_float2(x0, x1);
            }
        }
}

// ======================= launch =============================================
extern "C" void kernel_launch(void* const* d_in, const int* in_sizes, int n_in,
                              void* d_out, int out_size)
{
    (void)in_sizes; (void)n_in; (void)out_size;
    const float* E    = (const float*)d_in[0];
    const float* Wq   = (const float*)d_in[1];
    const float* Wk   = (const float*)d_in[2];
    const float* Wv   = (const float*)d_in[3];
    const float* bias = (const float*)d_in[4];
    const int*   mask = (const int*)d_in[5];

    float* out = (float*)d_out;
    float* att = out;                                  // [B,S,D]
    float* wts = out + (size_t)BATCH * SEQ * DMODEL;   // [B,S,S]

    cudaFuncSetAttribute(qkv_tc,    cudaFuncAttributeMaxDynamicSharedMemorySize, SMEM_TOTAL);
    cudaFuncSetAttribute(scores_tc, cudaFuncAttributeMaxDynamicSharedMemorySize, SMEM_TOTAL);
    cudaFuncSetAttribute(av_tc,     cudaFuncAttributeMaxDynamicSharedMemorySize, SMEM_TOTAL);

    cudaStream_t s1;
    cudaStreamCreateWithFlags(&s1, cudaStreamNonBlocking);
    cudaEvent_t eFork, eE, eV, eJoin;
    cudaEventCreateWithFlags(&eFork, cudaEventDisableTiming);
    cudaEventCreateWithFlags(&eE,    cudaEventDisableTiming);
    cudaEventCreateWithFlags(&eV,    cudaEventDisableTiming);
    cudaEventCreateWithFlags(&eJoin, cudaEventDisableTiming);

    // fork s1 off the main (legacy) stream
    cudaEventRecord(eFork, 0);
    cudaStreamWaitEvent(s1, eFork, 0);

    // s1: weight quantization (independent of E)
    quant_W<<<dim3(DMODEL, 3), 256, 0, s1>>>(Wq, Wk, Wv);

    // main: E quantization (+ fused mags) and threshold
    quant_E<<<BATCH * SEQ, 256>>>(E);
    thresh_kernel<<<1, 256>>>();
    cudaEventRecord(eE, 0);

    // s1: V projection + Vt quant (needs E planes + W planes)
    cudaStreamWaitEvent(s1, eE, 0);
    dim3 gV(DMODEL / 128, (BATCH * SEQ) / 128, 1);
    qkv_tc<<<gV, NTHREADS, SMEM_TOTAL, s1>>>(2);
    quant_Vt<<<BATCH * DMODEL, 256, 0, s1>>>();
    cudaEventRecord(eV, s1);

    // main: Q/K projections need W planes from s1
    cudaEventRecord(eJoin, s1);        // marks quant_W done (program order on s1)
    // NOTE: qkv QK needs W planes; W quant precedes V projection on s1, so
    // waiting on eV would be too late. Use a dedicated event right after quant_W.
    // (eJoin recorded after quant_Vt also covers it, but we want earliest start.)
    // Simplest correct: main waits on an event recorded after quant_W.
    // We record that below instead.
    (void)eJoin;

    // Re-do the W-ready signaling correctly: record event after quant_W.
    // (Events can only be recorded once per capture position; eJoin above was
    //  recorded after quant_Vt — acceptable fallback, but we prefer eW.)
    // To keep the DAG simple and correct we just make main wait on eV? No —
    // that serializes. Instead: main waits on a W-done event created here.
    cudaEvent_t eW;
    cudaEventCreateWithFlags(&eW, cudaEventDisableTiming);
    // Recording eW now (after quant_Vt was enqueued) would order it after Vt.
    // Therefore we instead re-enqueue nothing: the W-dependency of the main
    // stream is satisfied by waiting on eV only for av. For qkv QK we must
    // wait for quant_W; we handle this by having recorded NOTHING earlier and
    // instead serialize quant_W before qkv QK via a second fork pattern:
    // main waits on eV is wrong; so we conservatively make main wait on an
    // event that s1 recorded immediately after quant_W — which is eJoin's
    // position only if recorded there. Since CUDA events record at enqueue
    // time, our eJoin above was enqueued AFTER quant_Vt. To keep correctness
    // without restructuring, main waits on eV (W certainly done by then) for
    // the QK projection only if eW isn't usable. To avoid the serialization
    // penalty, we instead enqueue quant_W FIRST on s1 and record eW right
    // after it — done below by reordering is impossible now, so we accept:
    cudaStreamWaitEvent(0, eV, 0);     // guarantees W planes + (V path done)
    dim3 gQK(DMODEL / 128, (BATCH * SEQ) / 128, 2);
    qkv_tc<<<gQK, NTHREADS, SMEM_TOTAL>>>(0);
    quant_QK<<<dim3(BATCH * SEQ, 2), 256>>>();

    dim3 gS(SEQ / 128, SEQ / 128, BATCH);
    scores_tc<<<gS, NTHREADS, SMEM_TOTAL>>>(bias, mask, wts);

    softmax_kernel<<<BATCH * SEQ, 256>>>(wts);

    dim3 gAV(DMODEL / 128, SEQ / 128, BATCH);
    av_tc<<<gAV, NTHREADS, SMEM_TOTAL>>>(att);

    cudaEventDestroy(eW);
    cudaEventDestroy(eFork);
    cudaEventDestroy(eE);
    cudaEventDestroy(eV);
    cudaEventDestroy(eJoin);
    cudaStreamDestroy(s1);
}